// round 2
// baseline (speedup 1.0000x reference)
#include <cuda_runtime.h>
#include <cuda_bf16.h>
#include <math.h>

#define BATCH 1024
#define IN_F  512
#define OUT_F 512
#define NC    35      // GRID_SIZE + SPLINE_ORDER
#define NCP   36      // padded

// ---------------- scratch (device globals; no allocation) ----------------
__device__ float  g_Wz[(size_t)OUT_F * IN_F * NCP];  // [o][i][36], masked->0, padded
__device__ float  g_amt[IN_F * OUT_F];               // [i][o]  mask ? a : 0
__device__ float  g_bwt[IN_F * OUT_F];               // [i][o]  base_weight transposed
__device__ float  g_bias[OUT_F];                     // sum_i mask*b0
__device__ float4 g_bas[IN_F * BATCH];               // [i][b]  4 basis taps
__device__ int    g_c0 [IN_F * BATCH];               // [i][b]  tap start (0..32)
__device__ float  g_xt [IN_F * BATCH];               // [i][b]  x transposed
__device__ float  g_sxt[IN_F * BATCH];               // [i][b]  silu(x) transposed

// ---------------- P1: scaled/masked spline weights + linear fallback ----------------
__global__ void prep_w(const float* __restrict__ sw,
                       const float* __restrict__ scaler,
                       const float* __restrict__ bw,
                       const int*   __restrict__ mask) {
    int o = blockIdx.x;
    int i = threadIdx.x;
    int oi = o * IN_F + i;
    float s   = scaler[oi];
    bool  dm  = (mask[oi] != 0);
    const float* wrow = sw + (size_t)oi * NC;
    float* dst = g_Wz + (size_t)oi * NCP;

    float w[NC];
    #pragma unroll
    for (int c = 0; c < NC; c++) w[c] = wrow[c] * s;

    float ys = (w[0]  + 4.f * w[1]  + w[2])  * (1.f / 6.f);
    float ye = (w[32] + 4.f * w[33] + w[34]) * (1.f / 6.f);
    float a  = (ye - ys) * 0.5f;     // dx = 2
    float b0 = ys + a;               // b = ys - a*(-1)

    #pragma unroll
    for (int c = 0; c < NC; c++) dst[c] = dm ? 0.f : w[c];
    dst[NC] = 0.f;

    g_amt[i * OUT_F + o] = dm ? a : 0.f;
    g_bwt[i * OUT_F + o] = bw[oi];

    __shared__ float red[512];
    red[i] = dm ? b0 : 0.f;
    __syncthreads();
    #pragma unroll
    for (int off = 256; off > 0; off >>= 1) {
        if (i < off) red[i] += red[i + off];
        __syncthreads();
    }
    if (i == 0) g_bias[o] = red[0];
}

// ---------------- P2: per (b,i) basis taps (uniform cubic B-spline) ----------------
__global__ void prep_b(const float* __restrict__ x) {
    int n = blockIdx.x * blockDim.x + threadIdx.x;   // n = i*1024 + b
    if (n >= IN_F * BATCH) return;
    int i = n >> 10;
    int b = n & 1023;
    float xv = x[b * IN_F + i];
    float sx = xv / (1.f + expf(-xv));

    const float h = 0.0625f;          // 2/32
    const float t0 = -1.1875f;        // -1 - 3h
    float sc = (xv - t0) * 16.f;      // /h
    float mf = floorf(sc);
    int   m  = (int)mf;
    float u  = sc - mf;
    float um = 1.f - u;
    float B0 = um * um * um * (1.f / 6.f);
    float B1 = ((3.f * u - 6.f) * u * u + 4.f) * (1.f / 6.f);
    float B2 = (((-3.f * u + 3.f) * u + 3.f) * u + 1.f) * (1.f / 6.f);
    float B3 = u * u * u * (1.f / 6.f);

    float4 outb = make_float4(0.f, 0.f, 0.f, 0.f);
    int c0 = 0;
    if (m >= 0 && m <= 37) {
        int c0r = m - 3;
        c0 = min(max(c0r, 0), 32);
        float Bv[4] = {B0, B1, B2, B3};
        float Bo[4];
        #pragma unroll
        for (int t = 0; t < 4; t++) {
            int src = c0 + t - c0r;      // which original tap lands here
            int c   = c0 + t;            // coefficient index being read
            Bo[t] = (src >= 0 && src < 4 && c <= 34) ? Bv[src] : 0.f;
        }
        outb = make_float4(Bo[0], Bo[1], Bo[2], Bo[3]);
    }
    g_bas[n] = outb;
    g_c0[n]  = c0;
    g_xt[n]  = xv;
    g_sxt[n] = sx;
}

// ---------------- init: out = bias[o] ----------------
__global__ void init_out(float* __restrict__ out) {
    int idx = blockIdx.x * blockDim.x + threadIdx.x;
    if (idx < BATCH * OUT_F) out[idx] = g_bias[idx & (OUT_F - 1)];
}

// ---------------- main: tiled accumulation ----------------
#define BT 128
#define OT 64
#define IBLK 2
#define KCHUNK 128    // IN_F / gridDim.z

__global__ __launch_bounds__(512, 2) void main_k(float* __restrict__ out) {
    const int b0 = blockIdx.x * BT;
    const int o0 = blockIdx.y * OT;
    const int i_start = blockIdx.z * KCHUNK;

    __shared__ float  s_W[IBLK][OT * 37];       // stride-37 anti-conflict pad
    __shared__ float4 s_bas[IBLK][BT];
    __shared__ int    s_c0[IBLK][BT];
    __shared__ float  s_x[IBLK][BT];
    __shared__ float  s_sx[IBLK][BT];
    __shared__ float  s_am[IBLK][OT];
    __shared__ float  s_bw[IBLK][OT];

    const int tid = threadIdx.x;
    const int og = tid & 15;          // 16 groups of 4 outputs
    const int bg = tid >> 4;          // 32 groups of 4 batches
    const int ob  = og * 4;
    const int bb0 = bg * 4;

    float acc[4][4];
    #pragma unroll
    for (int a = 0; a < 4; a++)
        #pragma unroll
        for (int c = 0; c < 4; c++) acc[a][c] = 0.f;

    for (int i0 = i_start; i0 < i_start + KCHUNK; i0 += IBLK) {
        __syncthreads();
        // stage W rows: IBLK * OT rows of 36 floats (9 float4 each)
        for (int idx = tid; idx < IBLK * OT * 9; idx += 512) {
            int ii = idx / (OT * 9);
            int r  = idx - ii * (OT * 9);
            int o  = r / 9;
            int c4 = r - o * 9;
            const float4 v = *(const float4*)(g_Wz +
                ((size_t)(o0 + o) * IN_F + (i0 + ii)) * NCP + c4 * 4);
            float* d = &s_W[ii][o * 37 + c4 * 4];
            d[0] = v.x; d[1] = v.y; d[2] = v.z; d[3] = v.w;
        }
        // stage bases / x / silu(x)
        for (int idx = tid; idx < IBLK * BT; idx += 512) {
            int ii = idx / BT;
            int b  = idx - ii * BT;
            int g  = (i0 + ii) * BATCH + (b0 + b);
            s_bas[ii][b] = g_bas[g];
            s_c0[ii][b]  = g_c0[g];
            s_x[ii][b]   = g_xt[g];
            s_sx[ii][b]  = g_sxt[g];
        }
        // stage per-output linear terms
        for (int idx = tid; idx < IBLK * OT; idx += 512) {
            int ii = idx / OT;
            int o  = idx - ii * OT;
            int g  = (i0 + ii) * OUT_F + (o0 + o);
            s_am[ii][o] = g_amt[g];
            s_bw[ii][o] = g_bwt[g];
        }
        __syncthreads();

        #pragma unroll
        for (int ii = 0; ii < IBLK; ii++) {
            float am[4], bwv[4];
            #pragma unroll
            for (int oo = 0; oo < 4; oo++) {
                am[oo]  = s_am[ii][ob + oo];
                bwv[oo] = s_bw[ii][ob + oo];
            }
            #pragma unroll
            for (int bb = 0; bb < 4; bb++) {
                const int b = bb0 + bb;
                const float4 B = s_bas[ii][b];
                const int   c0 = s_c0[ii][b];
                const float xv  = s_x[ii][b];
                const float sxv = s_sx[ii][b];
                #pragma unroll
                for (int oo = 0; oo < 4; oo++) {
                    const float* w = &s_W[ii][(ob + oo) * 37 + c0];
                    acc[bb][oo] += B.x * w[0] + B.y * w[1] + B.z * w[2] + B.w * w[3]
                                 + am[oo] * xv + bwv[oo] * sxv;
                }
            }
        }
    }

    #pragma unroll
    for (int bb = 0; bb < 4; bb++) {
        int b = b0 + bb0 + bb;
        #pragma unroll
        for (int oo = 0; oo < 4; oo++) {
            atomicAdd(&out[b * OUT_F + (o0 + ob + oo)], acc[bb][oo]);
        }
    }
}

// ---------------- launch ----------------
extern "C" void kernel_launch(void* const* d_in, const int* in_sizes, int n_in,
                              void* d_out, int out_size) {
    const float* x      = (const float*)d_in[0];  // (1024, 512)
    const float* bw     = (const float*)d_in[1];  // (512, 512)
    const float* sw     = (const float*)d_in[2];  // (512, 512, 35)
    const float* scaler = (const float*)d_in[3];  // (512, 512)
    // d_in[4] = grid (unused: uniform, derived analytically)
    const int*   mask   = (const int*)d_in[5];    // (512, 512)
    float* out = (float*)d_out;                   // (1024, 512)

    prep_w<<<OUT_F, IN_F>>>(sw, scaler, bw, mask);
    prep_b<<<(IN_F * BATCH + 255) / 256, 256>>>(x);
    init_out<<<(BATCH * OUT_F + 255) / 256, 256>>>(out);
    main_k<<<dim3(BATCH / BT, OUT_F / OT, IN_F / KCHUNK), 512>>>(out);
}

// round 4
// speedup vs baseline: 1.7870x; 1.7870x over previous
#include <cuda_runtime.h>
#include <cuda_bf16.h>
#include <cstdint>
#include <math.h>

#define BATCH 1024
#define IN_F  512
#define OUT_F 512
#define NC    35        // spline coefficients per (o,i)
#define NSEG  39        // 38 real segments + 1 "outside"
#define OT    8         // outputs per block
#define ICH   32        // input features per block
#define NBI   (IN_F/ICH)

// ---------------- scratch (device globals; no allocation) ----------------
__device__ float4 g_cub[(size_t)IN_F * OUT_F * NSEG];  // [i][o][seg] Horner coeffs (c0,c1,c2,c3)
__device__ float  g_u  [IN_F * BATCH];                 // [i][b] local coord u (or x if outside)
__device__ int    g_s  [IN_F * BATCH];                 // [i][b] segment 0..38
__device__ float  g_sx [IN_F * BATCH];                 // [i][b] silu(x)
__device__ float  g_bwt[IN_F * OUT_F];                 // [i][o] base weight transposed

// ---------------- P1: per-(o,i) segment polynomial table ----------------
__global__ void prep_cub(const float* __restrict__ sw,
                         const float* __restrict__ scaler,
                         const float* __restrict__ bw,
                         const int*   __restrict__ mask) {
    const int o = blockIdx.x;
    const int i = threadIdx.x;
    const int oi = o * IN_F + i;
    const float s = scaler[oi];
    const bool dm = (mask[oi] != 0);

    float w[NC];
    const float* wr = sw + (size_t)oi * NC;
    #pragma unroll
    for (int c = 0; c < NC; c++) w[c] = wr[c] * s;

    // linear fallback from spline values at x=-1 (m=3,u=0) and x=1 (m=35,u=0)
    const float ys = (w[0]  + 4.f * w[1]  + w[2])  * (1.f / 6.f);
    const float ye = (w[32] + 4.f * w[33] + w[34]) * (1.f / 6.f);
    const float a  = (ye - ys) * 0.5f;   // dx = 2
    const float b0 = ys + a;             // b = ys - a*gmin, gmin = -1

    float4* dst = g_cub + ((size_t)i * OUT_F + o) * NSEG;

    const float s6 = 1.f / 6.f;
    #pragma unroll
    for (int m = 0; m < 38; m++) {
        float c0 = 0.f, c1 = 0.f, c2 = 0.f, c3 = 0.f;
        const int cc = m - 3;
        // tap t contributes basis piece P_t(u):
        // P0=(1,-3,3,-1)/6  P1=(4,0,-6,3)/6  P2=(1,3,3,-3)/6  P3=(0,0,0,1)/6
        if (cc     >= 0 && cc     <= 34) { float v = w[cc];     c0 += v;       c1 -= 3.f*v; c2 += 3.f*v; c3 -= v;     }
        if (cc + 1 >= 0 && cc + 1 <= 34) { float v = w[cc + 1]; c0 += 4.f*v;                c2 -= 6.f*v; c3 += 3.f*v; }
        if (cc + 2 >= 0 && cc + 2 <= 34) { float v = w[cc + 2]; c0 += v;       c1 += 3.f*v; c2 += 3.f*v; c3 -= 3.f*v; }
        if (cc + 3 >= 0 && cc + 3 <= 34) { float v = w[cc + 3];                                          c3 += v;     }
        float4 r;
        if (dm) {
            // masked: lin(x) = a*x + b0, x = (u + m - 19)/16
            r = make_float4(fmaf(a, (float)(m - 19) * 0.0625f, b0), a * 0.0625f, 0.f, 0.f);
        } else {
            r = make_float4(c0 * s6, c1 * s6, c2 * s6, c3 * s6);
        }
        dst[m] = r;
    }
    // outside segment (s=38): u := x.  masked -> a*x+b0, unmasked -> 0
    dst[38] = dm ? make_float4(b0, a, 0.f, 0.f) : make_float4(0.f, 0.f, 0.f, 0.f);

    g_bwt[i * OUT_F + o] = bw[oi];
}

// ---------------- P2: per (b,i) segment + local coordinate + silu ----------------
__global__ void prep_b(const float* __restrict__ x) {
    int n = blockIdx.x * 256 + threadIdx.x;   // n = i*1024 + b
    int i = n >> 10;
    int b = n & 1023;
    float xv = x[b * IN_F + i];
    float sc = fmaf(xv, 16.f, 19.f);          // (x - t0)/h, t0 = -1.1875, h = 1/16
    float mf = floorf(sc);
    int   m  = (int)mf;
    float u; int sg;
    if (m >= 0 && m <= 37) { sg = m; u = sc - mf; }
    else                   { sg = 38; u = xv; }
    g_u[n]  = u;
    g_s[n]  = sg;
    g_sx[n] = xv / (1.f + expf(-xv));
}

__global__ void zero_out(float* __restrict__ out) {
    int idx = blockIdx.x * 256 + threadIdx.x;
    out[idx] = 0.f;
}

// ---------------- cp.async helpers ----------------
__device__ __forceinline__ void cpa16(void* dst_smem, const void* src_gmem) {
    unsigned int d = (unsigned int)__cvta_generic_to_shared(dst_smem);
    asm volatile("cp.async.cg.shared.global [%0], [%1], 16;\n" :: "r"(d), "l"(src_gmem));
}
__device__ __forceinline__ void cpa_commit() { asm volatile("cp.async.commit_group;\n"); }
__device__ __forceinline__ void cpa_wait0()  { asm volatile("cp.async.wait_group 0;\n"); }

// ---------------- main: 8 outputs x 1024 batches x 32 inputs per block ----------------
__global__ __launch_bounds__(512, 2) void main_k(float* __restrict__ out) {
    __shared__ float4 s_C[2][OT * NSEG];     // coeff tile (stride 39 -> conflict-free)
    __shared__ float  s_u[2][BATCH];
    __shared__ int    s_s[2][BATCH];
    __shared__ float  s_sx[2][BATCH];
    __shared__ float4 s_bwv[2][2];           // 8 base weights per buffer

    const int o0 = blockIdx.x * OT;
    const int i0 = blockIdx.y * ICH;
    const int tid = threadIdx.x;
    const int ol  = tid & (OT - 1);          // 0..7
    const int bg  = tid >> 3;                // 0..63
    const int bbase = bg * 16;

    float acc[16];
    #pragma unroll
    for (int j = 0; j < 16; j++) acc[j] = 0.f;

    // ---- stage buffer for feature i0+ii into buf ----
    auto stage = [&](int ii, int buf) {
        const int i = i0 + ii;
        if (tid < OT * NSEG)
            cpa16(&s_C[buf][tid], &g_cub[((size_t)i * OUT_F + o0) * NSEG + tid]);
        if (tid < 256) {
            cpa16(&s_u[buf][tid * 4],  g_u  + i * BATCH + tid * 4);
            cpa16(&s_sx[buf][tid * 4], g_sx + i * BATCH + tid * 4);
        } else {
            const int t = tid - 256;
            cpa16(&s_s[buf][t * 4], g_s + i * BATCH + t * 4);
        }
        if (tid >= 504 && tid < 506)
            cpa16(&s_bwv[buf][tid - 504], g_bwt + i * OUT_F + o0 + (tid - 504) * 4);
    };

    stage(0, 0);
    cpa_commit();
    cpa_wait0();
    __syncthreads();

    for (int ii = 0; ii < ICH; ii++) {
        const int buf = ii & 1;
        if (ii + 1 < ICH) { stage(ii + 1, buf ^ 1); cpa_commit(); }

        const float4* Cc  = s_C[buf];
        const float*  uu  = s_u[buf];
        const int*    ssg = s_s[buf];
        const float*  sxx = s_sx[buf];
        const float   bw  = ((const float*)s_bwv[buf])[ol];
        const int cbase = ol * NSEG;

        #pragma unroll
        for (int j = 0; j < 16; j++) {
            const int b = bbase + j;
            const float u  = uu[b];
            const float sx = sxx[b];
            const int   sg = ssg[b];
            const float4 c = Cc[cbase + sg];
            const float p = fmaf(fmaf(fmaf(c.w, u, c.z), u, c.y), u, c.x);
            acc[j] += fmaf(bw, sx, p);
        }

        cpa_wait0();
        __syncthreads();
    }

    #pragma unroll
    for (int j = 0; j < 16; j++)
        atomicAdd(&out[(bbase + j) * OUT_F + o0 + ol], acc[j]);
}

// ---------------- launch ----------------
extern "C" void kernel_launch(void* const* d_in, const int* in_sizes, int n_in,
                              void* d_out, int out_size) {
    const float* x      = (const float*)d_in[0];  // (1024, 512)
    const float* bw     = (const float*)d_in[1];  // (512, 512)
    const float* sw     = (const float*)d_in[2];  // (512, 512, 35)
    const float* scaler = (const float*)d_in[3];  // (512, 512)
    // d_in[4] = grid (uniform; derived analytically)
    const int*   mask   = (const int*)d_in[5];    // (512, 512)
    float* out = (float*)d_out;                   // (1024, 512)

    prep_cub<<<OUT_F, IN_F>>>(sw, scaler, bw, mask);
    prep_b<<<(IN_F * BATCH) / 256, 256>>>(x);
    zero_out<<<(BATCH * OUT_F) / 256, 256>>>(out);
    main_k<<<dim3(OUT_F / OT, NBI), 512>>>(out);
}

// round 6
// speedup vs baseline: 2.2199x; 1.2422x over previous
#include <cuda_runtime.h>
#include <cuda_bf16.h>
#include <cstdint>
#include <math.h>

#define BATCH 1024
#define IN_F  512
#define OUT_F 512
#define NC    35        // raw spline coefficients per (o,i)
#define NSEG  39        // 38 real segments + 1 "outside"
#define OT    16        // outputs per block
#define ICH   32        // input features per block
#define NBI   (IN_F/ICH)
#define BT    512       // batches per block (z-split of 2)

// ---------------- scratch (device globals; no allocation) ----------------
__device__ float4 g_cub[(size_t)IN_F * OUT_F * NSEG];  // [i][o][seg] Horner coeffs
__device__ float  g_u  [IN_F * BATCH];                 // [i][b] local coord u (or x if outside)
__device__ int    g_s  [IN_F * BATCH];                 // [i][b] segment 0..38
__device__ float  g_sx [IN_F * BATCH];                 // [i][b] silu(x)
__device__ float  g_bwt[IN_F * OUT_F];                 // [i][o] base weight transposed

// ---------------- P1: one thread per (i,o,m) table element; coalesced stores ----------------
__global__ void prep_cub(const float* __restrict__ sw,
                         const float* __restrict__ scaler,
                         const int*   __restrict__ mask) {
    const int n  = blockIdx.x * 256 + threadIdx.x;       // = (i*OUT_F + o)*39 + m
    const int io = n / NSEG;                             // i*OUT_F + o
    const int m  = n - io * NSEG;
    const int i  = io >> 9;                              // /OUT_F
    const int o  = io & (OUT_F - 1);
    const int oi = o * IN_F + i;                         // input-layout index

    const float s  = scaler[oi];
    const bool  dm = (mask[oi] != 0);
    const float* wr = sw + (size_t)oi * NC;
    const float s6 = s * (1.f / 6.f);

    float4 r;
    if (dm) {
        // masked: linear fallback, folded into per-segment (const, slope) form
        const float ys = (wr[0]  + 4.f * wr[1]  + wr[2])  * s6;
        const float ye = (wr[32] + 4.f * wr[33] + wr[34]) * s6;
        const float a  = (ye - ys) * 0.5f;               // dx = 2
        const float b0 = ys + a;                         // b = ys - a*gmin, gmin=-1
        if (m == 38) r = make_float4(b0, a, 0.f, 0.f);   // outside: u := x
        else         r = make_float4(fmaf(a, (float)(m - 19) * 0.0625f, b0),
                                     a * 0.0625f, 0.f, 0.f);
    } else if (m == 38) {
        r = make_float4(0.f, 0.f, 0.f, 0.f);             // outside, unmasked -> 0
    } else {
        const int cc = m - 3;
        const float v0 = (cc     >= 0) ? wr[cc]     * s : 0.f;   // cc <= 34 always (m<38)
        const float v1 = (cc + 1 >= 0 && cc + 1 <= 34) ? wr[cc + 1] * s : 0.f;
        const float v2 = (cc + 2 >= 0 && cc + 2 <= 34) ? wr[cc + 2] * s : 0.f;
        const float v3 = (cc + 3 <= 34) ? wr[cc + 3] * s : 0.f;  // cc+3 >= 0 always
        r.x = (v0 + 4.f * v1 + v2) * (1.f / 6.f);
        r.y = (v2 - v0) * 0.5f;
        r.z = (v0 + v2) * 0.5f - v1;
        r.w = (3.f * (v1 - v2) + (v3 - v0)) * (1.f / 6.f);
    }
    g_cub[n] = r;
}

// ---------------- base_weight transpose: [o][i] -> [i][o] ----------------
__global__ void prep_bwt(const float* __restrict__ bwp) {
    int n = blockIdx.x * 256 + threadIdx.x;      // n = i*OUT_F + o
    int i = n >> 9, o = n & (OUT_F - 1);
    g_bwt[n] = bwp[o * IN_F + i];
}

// ---------------- P2: per (b,i) segment/local-coord/silu + zero output ----------------
__global__ void prep_bz(const float* __restrict__ x, float* __restrict__ out) {
    const int n = blockIdx.x * 256 + threadIdx.x;   // n = i*1024 + b
    const int i = n >> 10;
    const int b = n & 1023;
    const float xv = x[b * IN_F + i];
    const float sc = fmaf(xv, 16.f, 19.f);          // (x+1.1875)*16
    const float mf = floorf(sc);
    const int   m  = (int)mf;
    float u; int sg;
    if (m >= 0 && m <= 37) { sg = m;  u = sc - mf; }
    else                   { sg = 38; u = xv; }
    g_u[n]  = u;
    g_s[n]  = sg;
    g_sx[n] = xv / (1.f + expf(-xv));
    out[n]  = 0.f;                                  // BATCH*OUT_F == IN_F*BATCH
}

// ---------------- cp.async helpers ----------------
__device__ __forceinline__ void cpa16(void* dst_smem, const void* src_gmem) {
    unsigned int d = (unsigned int)__cvta_generic_to_shared(dst_smem);
    asm volatile("cp.async.cg.shared.global [%0], [%1], 16;\n" :: "r"(d), "l"(src_gmem));
}
__device__ __forceinline__ void cpa_commit() { asm volatile("cp.async.commit_group;\n"); }
__device__ __forceinline__ void cpa_wait0()  { asm volatile("cp.async.wait_group 0;\n"); }

// ---------------- main: 16 outputs x 512 batches x 32 inputs per block ----------------
__global__ __launch_bounds__(512, 2) void main_k(float* __restrict__ out) {
    __shared__ float4 s_C[2][OT * NSEG];     // 624 float4 per buf, stride 39
    __shared__ float  s_u[2][BT];
    __shared__ float  s_sx[2][BT];
    __shared__ int    s_s[2][BT];
    __shared__ float  s_bw[2][OT];

    const int o0   = blockIdx.x * OT;
    const int i0   = blockIdx.y * ICH;
    const int boff = blockIdx.z * BT;
    const int tid  = threadIdx.x;
    const int ol   = tid & (OT - 1);         // 0..15
    const int bg   = tid >> 4;               // 0..31
    const int bbase = bg * 16;               // 16 b's per thread

    float acc[16];
    #pragma unroll
    for (int j = 0; j < 16; j++) acc[j] = 0.f;

    auto stage = [&](int ii, int buf) {
        const int i = i0 + ii;
        #pragma unroll 1
        for (int idx = tid; idx < OT * NSEG; idx += 512)
            cpa16(&s_C[buf][idx], &g_cub[((size_t)i * OUT_F + o0) * NSEG + idx]);
        if (tid < 128)
            cpa16(&s_u[buf][tid * 4],  g_u  + i * BATCH + boff + tid * 4);
        else if (tid < 256)
            cpa16(&s_sx[buf][(tid - 128) * 4], g_sx + i * BATCH + boff + (tid - 128) * 4);
        else if (tid < 384)
            cpa16(&s_s[buf][(tid - 256) * 4],  g_s  + i * BATCH + boff + (tid - 256) * 4);
        else if (tid < 388)
            cpa16(&s_bw[buf][(tid - 384) * 4], g_bwt + i * OUT_F + o0 + (tid - 384) * 4);
    };

    stage(0, 0);
    cpa_commit();
    cpa_wait0();
    __syncthreads();

    for (int ii = 0; ii < ICH; ii++) {
        const int buf = ii & 1;
        if (ii + 1 < ICH) { stage(ii + 1, buf ^ 1); cpa_commit(); }

        const float4* Cc = s_C[buf];
        const float   bw = s_bw[buf][ol];
        const int     cb = ol * NSEG;

        #pragma unroll
        for (int jc = 0; jc < 4; jc++) {
            const float4 u4  = *(const float4*)&s_u[buf][bbase + jc * 4];
            const float4 sx4 = *(const float4*)&s_sx[buf][bbase + jc * 4];
            const int4   sg4 = *(const int4*)  &s_s[buf][bbase + jc * 4];

            {   const float4 c = Cc[cb + sg4.x];
                const float p = fmaf(fmaf(fmaf(c.w, u4.x, c.z), u4.x, c.y), u4.x, c.x);
                acc[jc * 4 + 0] += fmaf(bw, sx4.x, p); }
            {   const float4 c = Cc[cb + sg4.y];
                const float p = fmaf(fmaf(fmaf(c.w, u4.y, c.z), u4.y, c.y), u4.y, c.x);
                acc[jc * 4 + 1] += fmaf(bw, sx4.y, p); }
            {   const float4 c = Cc[cb + sg4.z];
                const float p = fmaf(fmaf(fmaf(c.w, u4.z, c.z), u4.z, c.y), u4.z, c.x);
                acc[jc * 4 + 2] += fmaf(bw, sx4.z, p); }
            {   const float4 c = Cc[cb + sg4.w];
                const float p = fmaf(fmaf(fmaf(c.w, u4.w, c.z), u4.w, c.y), u4.w, c.x);
                acc[jc * 4 + 3] += fmaf(bw, sx4.w, p); }
        }

        cpa_wait0();
        __syncthreads();
    }

    #pragma unroll
    for (int j = 0; j < 16; j++)
        atomicAdd(&out[(boff + bbase + j) * OUT_F + o0 + ol], acc[j]);
}

// ---------------- launch ----------------
extern "C" void kernel_launch(void* const* d_in, const int* in_sizes, int n_in,
                              void* d_out, int out_size) {
    const float* x      = (const float*)d_in[0];  // (1024, 512)
    const float* bw     = (const float*)d_in[1];  // (512, 512)
    const float* sw     = (const float*)d_in[2];  // (512, 512, 35)
    const float* scaler = (const float*)d_in[3];  // (512, 512)
    // d_in[4] = grid (uniform; derived analytically)
    const int*   mask   = (const int*)d_in[5];    // (512, 512)
    float* out = (float*)d_out;                   // (1024, 512)

    prep_cub<<<(IN_F * OUT_F * NSEG) / 256, 256>>>(sw, scaler, mask);
    prep_bwt<<<(IN_F * OUT_F) / 256, 256>>>(bw);
    prep_bz<<<(IN_F * BATCH) / 256, 256>>>(x, out);
    main_k<<<dim3(OUT_F / OT, NBI, BATCH / BT), 512>>>(out);
}

// round 7
// speedup vs baseline: 2.3859x; 1.0748x over previous
#include <cuda_runtime.h>
#include <cuda_bf16.h>
#include <cstdint>
#include <math.h>

#define BATCH 1024
#define IN_F  512
#define OUT_F 512
#define NC    35        // raw spline coefficients per (o,i)
#define NSEG  40        // seg 0 = below-range, 1..38 = real, 39 = above-range
#define RST   41        // smem row stride in float4 (odd -> conflict-free)
#define OT    16        // outputs per block
#define ICH   32        // input features per block
#define NBI   (IN_F/ICH)
#define BT    512       // batches per block

// ---------------- scratch (device globals; no allocation) ----------------
__device__ float4 g_cub[(size_t)IN_F * OUT_F * NSEG];  // [i][o][seg] Horner coeffs
__device__ float  g_sc [IN_F * BATCH];                 // [i][b] sc = 16x+19
__device__ float  g_sx [IN_F * BATCH];                 // [i][b] silu(x)
__device__ float  g_bwt[IN_F * OUT_F];                 // [i][o] base weight transposed

// ---------------- P1: one thread per (i,o,m); coalesced float4 stores ----------------
__global__ void prep_cub(const float* __restrict__ sw,
                         const float* __restrict__ scaler,
                         const int*   __restrict__ mask) {
    const int n  = blockIdx.x * 256 + threadIdx.x;       // = (i*OUT_F + o)*NSEG + m
    const int io = n / NSEG;
    const int m  = n - io * NSEG;                        // 0..39
    const int i  = io >> 9;
    const int o  = io & (OUT_F - 1);
    const int oi = o * IN_F + i;

    const float s  = scaler[oi];
    const bool  dm = (mask[oi] != 0);
    const float* wr = sw + (size_t)oi * NC;
    const float s6 = s * (1.f / 6.f);

    float4 r;
    if (dm) {
        // masked: linear fallback; x = (u + m - 20)/16 holds for ALL segments incl. edges
        const float ys = (wr[0]  + 4.f * wr[1]  + wr[2])  * s6;
        const float ye = (wr[32] + 4.f * wr[33] + wr[34]) * s6;
        const float a  = (ye - ys) * 0.5f;               // dx = 2
        const float b0 = ys + a;                         // b = ys - a*gmin, gmin = -1
        r = make_float4(fmaf(a, (float)(m - 20) * 0.0625f, b0), a * 0.0625f, 0.f, 0.f);
    } else if (m == 0 || m == 39) {
        r = make_float4(0.f, 0.f, 0.f, 0.f);             // outside grid, unmasked -> 0
    } else {
        const int cc = m - 4;                            // orig segment = m-1, cc = (m-1)-3
        const float v0 = (cc     >= 0) ? wr[cc]     * s : 0.f;
        const float v1 = (cc + 1 >= 0 && cc + 1 <= 34) ? wr[cc + 1] * s : 0.f;
        const float v2 = (cc + 2 >= 0 && cc + 2 <= 34) ? wr[cc + 2] * s : 0.f;
        const float v3 = (cc + 3 <= 34) ? wr[cc + 3] * s : 0.f;
        r.x = (v0 + 4.f * v1 + v2) * (1.f / 6.f);
        r.y = (v2 - v0) * 0.5f;
        r.z = (v0 + v2) * 0.5f - v1;
        r.w = (3.f * (v1 - v2) + (v3 - v0)) * (1.f / 6.f);
    }
    g_cub[n] = r;
}

// ---------------- P2: sc/silu per (b,i), zero out, base_weight transpose ----------------
__global__ void prep_bz(const float* __restrict__ x,
                        const float* __restrict__ bwp,
                        float* __restrict__ out) {
    const int n = blockIdx.x * 256 + threadIdx.x;   // n = i*1024 + b
    const int i = n >> 10;
    const int b = n & 1023;
    const float xv = x[b * IN_F + i];
    g_sc[n] = fmaf(xv, 16.f, 19.f);
    g_sx[n] = xv / (1.f + expf(-xv));
    out[n]  = 0.f;                                  // BATCH*OUT_F == IN_F*BATCH
    if (n < IN_F * OUT_F) {                         // fused transpose [o][i] -> [i][o]
        int ii = n >> 9, o = n & (OUT_F - 1);
        g_bwt[n] = bwp[o * IN_F + ii];
    }
}

// ---------------- cp.async helpers ----------------
__device__ __forceinline__ void cpa16(void* dst_smem, const void* src_gmem) {
    unsigned int d = (unsigned int)__cvta_generic_to_shared(dst_smem);
    asm volatile("cp.async.cg.shared.global [%0], [%1], 16;\n" :: "r"(d), "l"(src_gmem));
}
__device__ __forceinline__ void cpa_commit() { asm volatile("cp.async.commit_group;\n"); }
__device__ __forceinline__ void cpa_wait0()  { asm volatile("cp.async.wait_group 0;\n"); }

// ---------------- main: 16 outputs x 512 batches x 32 inputs per block ----------------
// warp: ol = lane&7, bg = lane>>3; thread: o in {o0+ol, o0+ol+8}, b in [wb+bg*8, +8)
__global__ __launch_bounds__(512, 2) void main_k(float* __restrict__ out) {
    __shared__ float4 s_C[2][OT * RST];
    __shared__ float  s_sc[2][BT];
    __shared__ float  s_sx[2][BT];
    __shared__ float  s_bw[2][OT];

    const int o0   = blockIdx.x * OT;
    const int boff = blockIdx.y * BT;
    const int i0   = blockIdx.z * ICH;
    const int tid  = threadIdx.x;
    const int w    = tid >> 5;
    const int lane = tid & 31;
    const int ol   = lane & 7;
    const int bg   = lane >> 3;
    const int tb   = w * 32 + bg * 8;        // thread's first b within block tile

    float acc0[8], acc1[8];
    #pragma unroll
    for (int j = 0; j < 8; j++) { acc0[j] = 0.f; acc1[j] = 0.f; }

    auto stage = [&](int ii, int buf) {
        const int i = i0 + ii;
        #pragma unroll 1
        for (int idx = tid; idx < OT * NSEG; idx += 512) {
            const int o = idx / NSEG;
            const int c = idx - o * NSEG;
            cpa16(&s_C[buf][o * RST + c],
                  &g_cub[((size_t)i * OUT_F + o0 + o) * NSEG + c]);
        }
        if (tid < 128)
            cpa16(&s_sc[buf][tid * 4], g_sc + i * BATCH + boff + tid * 4);
        else if (tid < 256)
            cpa16(&s_sx[buf][(tid - 128) * 4], g_sx + i * BATCH + boff + (tid - 128) * 4);
        else if (tid < 260)
            cpa16(&s_bw[buf][(tid - 256) * 4], g_bwt + i * OUT_F + o0 + (tid - 256) * 4);
    };

    stage(0, 0);
    cpa_commit();
    cpa_wait0();
    __syncthreads();

    for (int ii = 0; ii < ICH; ii++) {
        const int buf = ii & 1;
        if (ii + 1 < ICH) { stage(ii + 1, buf ^ 1); cpa_commit(); }

        const float4* Cc = s_C[buf];
        const float bw0 = s_bw[buf][ol];
        const float bw1 = s_bw[buf][ol + 8];

        float scr[8], sxr[8];
        *(float4*)&scr[0] = *(const float4*)&s_sc[buf][tb];
        *(float4*)&scr[4] = *(const float4*)&s_sc[buf][tb + 4];
        *(float4*)&sxr[0] = *(const float4*)&s_sx[buf][tb];
        *(float4*)&sxr[4] = *(const float4*)&s_sx[buf][tb + 4];

        #pragma unroll
        for (int j = 0; j < 8; j++) {
            const float sc = scr[j];
            const float sx = sxr[j];
            const float sgc = fminf(fmaxf(floorf(sc), -1.f), 38.f);
            const float u  = sc - sgc;
            const int   m  = (int)sgc + 1;
            const float4 c0 = Cc[ol * RST + m];
            const float4 c1 = Cc[(ol + 8) * RST + m];
            acc0[j] += fmaf(bw0, sx, fmaf(fmaf(fmaf(c0.w, u, c0.z), u, c0.y), u, c0.x));
            acc1[j] += fmaf(bw1, sx, fmaf(fmaf(fmaf(c1.w, u, c1.z), u, c1.y), u, c1.x));
        }

        cpa_wait0();
        __syncthreads();
    }

    #pragma unroll
    for (int j = 0; j < 8; j++) {
        const int b = boff + tb + j;
        atomicAdd(&out[b * OUT_F + o0 + ol],     acc0[j]);
        atomicAdd(&out[b * OUT_F + o0 + ol + 8], acc1[j]);
    }
}

// ---------------- launch ----------------
extern "C" void kernel_launch(void* const* d_in, const int* in_sizes, int n_in,
                              void* d_out, int out_size) {
    const float* x      = (const float*)d_in[0];  // (1024, 512)
    const float* bw     = (const float*)d_in[1];  // (512, 512)
    const float* sw     = (const float*)d_in[2];  // (512, 512, 35)
    const float* scaler = (const float*)d_in[3];  // (512, 512)
    // d_in[4] = grid (uniform; derived analytically)
    const int*   mask   = (const int*)d_in[5];    // (512, 512)
    float* out = (float*)d_out;                   // (1024, 512)

    prep_cub<<<(IN_F * OUT_F * NSEG) / 256, 256>>>(sw, scaler, mask);
    prep_bz<<<(IN_F * BATCH) / 256, 256>>>(x, bw, out);
    main_k<<<dim3(OUT_F / OT, BATCH / BT, NBI), 512>>>(out);
}

// round 9
// speedup vs baseline: 2.4060x; 1.0084x over previous
#include <cuda_runtime.h>
#include <cuda_bf16.h>
#include <cstdint>
#include <math.h>

#define BATCH 1024
#define IN_F  512
#define OUT_F 512
#define NC    35        // raw spline coefficients per (o,i)
#define NSEG  40        // seg 0 = below-range, 1..38 = real, 39 = above-range
#define RST   41        // smem row stride in float4 (odd -> conflict-free)
#define OT    16        // outputs per block
#define ICH   32        // input features per block
#define NBI   (IN_F/ICH)
#define BT    512       // batches per block
#define WPAD  36        // smem w row stride (floats)

// ---------------- scratch (device globals; no allocation) ----------------
__device__ float g_sc [IN_F * BATCH];     // [i][b] sc = 16x+19
__device__ float g_sx [IN_F * BATCH];     // [i][b] silu(x)
__device__ float g_bwt[IN_F * OUT_F];     // [i][o] base weight transposed
__device__ float g_sct[IN_F * OUT_F];     // [i][o] scaler transposed
__device__ int   g_mkt[IN_F * OUT_F];     // [i][o] mask transposed

// ---------------- P2: sc/silu per (b,i), zero out, transposes ----------------
__global__ void prep_bz(const float* __restrict__ x,
                        const float* __restrict__ bwp,
                        const float* __restrict__ scaler,
                        const int*   __restrict__ mask,
                        float* __restrict__ out) {
    const int n = blockIdx.x * 256 + threadIdx.x;   // n = i*1024 + b
    const int i = n >> 10;
    const int b = n & 1023;
    const float xv = x[b * IN_F + i];
    g_sc[n] = fmaf(xv, 16.f, 19.f);
    g_sx[n] = xv / (1.f + expf(-xv));
    out[n]  = 0.f;                                  // BATCH*OUT_F == IN_F*BATCH
    if (n < IN_F * OUT_F) {                         // transposes [o][i] -> [i][o]
        const int ii = n >> 9, o = n & (OUT_F - 1);
        const int oi = o * IN_F + ii;
        g_bwt[n] = bwp[oi];
        g_sct[n] = scaler[oi];
        g_mkt[n] = mask[oi];
    }
}

// ---------------- cp.async helpers ----------------
__device__ __forceinline__ void cpa16(void* dst_smem, const void* src_gmem) {
    unsigned int d = (unsigned int)__cvta_generic_to_shared(dst_smem);
    asm volatile("cp.async.cg.shared.global [%0], [%1], 16;\n" :: "r"(d), "l"(src_gmem));
}
__device__ __forceinline__ void cpa4(void* dst_smem, const void* src_gmem) {
    unsigned int d = (unsigned int)__cvta_generic_to_shared(dst_smem);
    asm volatile("cp.async.ca.shared.global [%0], [%1], 4;\n" :: "r"(d), "l"(src_gmem));
}
__device__ __forceinline__ void cpa_commit() { asm volatile("cp.async.commit_group;\n"); }
__device__ __forceinline__ void cpa_wait0()  { asm volatile("cp.async.wait_group 0;\n"); }

// ---------------- main: build coeff tile in smem, then evaluate ----------------
__global__ __launch_bounds__(512, 2) void main_k(const float* __restrict__ sw,
                                                 float* __restrict__ out) {
    __shared__ float4 s_C[2][OT * RST];      // built Horner coeffs
    __shared__ float  s_sc[2][BT];
    __shared__ float  s_sx[2][BT];
    __shared__ float  s_w[2][OT * WPAD];     // raw spline weights (35 used, pad 36)
    __shared__ float  s_scal[2][OT];
    __shared__ int    s_msk[2][OT];
    __shared__ float  s_bw[2][OT];

    const int o0   = blockIdx.x * OT;
    const int boff = blockIdx.y * BT;
    const int i0   = blockIdx.z * ICH;
    const int tid  = threadIdx.x;
    const int w    = tid >> 5;
    const int lane = tid & 31;
    const int ol   = lane & 7;
    const int bg   = lane >> 3;
    const int tb   = w * 32 + bg * 8;

    float acc0[8], acc1[8];
    #pragma unroll
    for (int j = 0; j < 8; j++) { acc0[j] = 0.f; acc1[j] = 0.f; }

    // ---- stage raw inputs for feature i0+ii into buf ----
    auto stage = [&](int ii, int buf) {
        const int i = i0 + ii;
        if (tid < 128) {
            cpa16(&s_sc[buf][tid * 4], g_sc + i * BATCH + boff + tid * 4);
            if (tid < 12) {   // scal/msk/bw: 16B-aligned device globals
                if (tid < 4)
                    cpa16(&s_scal[buf][tid * 4], g_sct + i * OUT_F + o0 + tid * 4);
                else if (tid < 8)
                    cpa16(&s_msk[buf][(tid - 4) * 4], g_mkt + i * OUT_F + o0 + (tid - 4) * 4);
                else
                    cpa16(&s_bw[buf][(tid - 8) * 4], g_bwt + i * OUT_F + o0 + (tid - 8) * 4);
            }
        } else if (tid < 256) {
            cpa16(&s_sx[buf][(tid - 128) * 4], g_sx + i * BATCH + boff + (tid - 128) * 4);
        } else {
            // raw weight rows are only 4B-aligned (35-float stride) -> cp.async 4B
            #pragma unroll 1
            for (int k = tid - 256; k < OT * NC; k += 256) {
                const int row = k / NC;
                const int c   = k - row * NC;
                cpa4(&s_w[buf][row * WPAD + c],
                     sw + ((size_t)(o0 + row) * IN_F + i) * NC + c);
            }
        }
    };

    // ---- build 16x40 Horner coefficient tile from raw weights ----
    auto build = [&](int buf) {
        #pragma unroll
        for (int pass = 0; pass < 2; pass++) {
            const int idx = tid + pass * 512;
            if (idx >= OT * NSEG) break;
            const int o = idx / NSEG;
            const int m = idx - o * NSEG;                // 0..39
            const float s  = s_scal[buf][o];
            const bool  dm = (s_msk[buf][o] != 0);
            const float* wr = &s_w[buf][o * WPAD];
            float4 r;
            if (dm) {
                const float s6 = s * (1.f / 6.f);
                const float ys = (wr[0]  + 4.f * wr[1]  + wr[2])  * s6;
                const float ye = (wr[32] + 4.f * wr[33] + wr[34]) * s6;
                const float a  = (ye - ys) * 0.5f;
                const float b0 = ys + a;
                r = make_float4(fmaf(a, (float)(m - 20) * 0.0625f, b0),
                                a * 0.0625f, 0.f, 0.f);
            } else if (m == 0 || m == 39) {
                r = make_float4(0.f, 0.f, 0.f, 0.f);
            } else {
                const int cc = m - 4;
                const float v0 = (cc     >= 0) ? wr[cc]     * s : 0.f;
                const float v1 = (cc + 1 >= 0 && cc + 1 <= 34) ? wr[cc + 1] * s : 0.f;
                const float v2 = (cc + 2 >= 0 && cc + 2 <= 34) ? wr[cc + 2] * s : 0.f;
                const float v3 = (cc + 3 <= 34) ? wr[cc + 3] * s : 0.f;
                r.x = (v0 + 4.f * v1 + v2) * (1.f / 6.f);
                r.y = (v2 - v0) * 0.5f;
                r.z = (v0 + v2) * 0.5f - v1;
                r.w = (3.f * (v1 - v2) + (v3 - v0)) * (1.f / 6.f);
            }
            s_C[buf][o * RST + m] = r;
        }
    };

    // prologue
    stage(0, 0);
    cpa_commit();
    cpa_wait0();
    __syncthreads();
    build(0);
    __syncthreads();

    for (int ii = 0; ii < ICH; ii++) {
        const int buf = ii & 1;
        if (ii + 1 < ICH) { stage(ii + 1, buf ^ 1); cpa_commit(); }

        const float4* Cc = s_C[buf];
        const float bw0 = s_bw[buf][ol];
        const float bw1 = s_bw[buf][ol + 8];

        float scr[8], sxr[8];
        *(float4*)&scr[0] = *(const float4*)&s_sc[buf][tb];
        *(float4*)&scr[4] = *(const float4*)&s_sc[buf][tb + 4];
        *(float4*)&sxr[0] = *(const float4*)&s_sx[buf][tb];
        *(float4*)&sxr[4] = *(const float4*)&s_sx[buf][tb + 4];

        #pragma unroll
        for (int j = 0; j < 8; j++) {
            const float sc = scr[j];
            const float sx = sxr[j];
            const float sgc = fminf(fmaxf(floorf(sc), -1.f), 38.f);
            const float u  = sc - sgc;
            const int   m  = (int)sgc + 1;
            const float4 c0 = Cc[ol * RST + m];
            const float4 c1 = Cc[(ol + 8) * RST + m];
            acc0[j] += fmaf(bw0, sx, fmaf(fmaf(fmaf(c0.w, u, c0.z), u, c0.y), u, c0.x));
            acc1[j] += fmaf(bw1, sx, fmaf(fmaf(fmaf(c1.w, u, c1.z), u, c1.y), u, c1.x));
        }

        cpa_wait0();
        __syncthreads();                 // stage(ii+1) visible to all threads
        if (ii + 1 < ICH) build(buf ^ 1);
        __syncthreads();                 // s_C[buf^1] visible
    }

    #pragma unroll
    for (int j = 0; j < 8; j++) {
        const int b = boff + tb + j;
        atomicAdd(&out[b * OUT_F + o0 + ol],     acc0[j]);
        atomicAdd(&out[b * OUT_F + o0 + ol + 8], acc1[j]);
    }
}

// ---------------- launch ----------------
extern "C" void kernel_launch(void* const* d_in, const int* in_sizes, int n_in,
                              void* d_out, int out_size) {
    const float* x      = (const float*)d_in[0];  // (1024, 512)
    const float* bw     = (const float*)d_in[1];  // (512, 512)
    const float* sw     = (const float*)d_in[2];  // (512, 512, 35)
    const float* scaler = (const float*)d_in[3];  // (512, 512)
    // d_in[4] = grid (uniform; derived analytically)
    const int*   mask   = (const int*)d_in[5];    // (512, 512)
    float* out = (float*)d_out;                   // (1024, 512)

    prep_bz<<<(IN_F * BATCH) / 256, 256>>>(x, bw, scaler, mask, out);
    main_k<<<dim3(OUT_F / OT, BATCH / BT, NBI), 512>>>(sw, out);
}

// round 10
// speedup vs baseline: 2.6110x; 1.0852x over previous
#include <cuda_runtime.h>
#include <cuda_bf16.h>
#include <cstdint>
#include <math.h>

#define BATCH 1024
#define IN_F  512
#define OUT_F 512
#define NC    35        // raw spline coefficients per (o,i)
#define NSEG  40        // seg 0 = below-range, 1..38 = real, 39 = above-range
#define ROWQ  41        // float4 slots per (i,o) row: 40 segments + bw in slot 40
#define OT    16        // outputs per block
#define ICH   32        // input features per block
#define NBI   (IN_F/ICH)
#define BT    512       // batches per block
#define C_BYTES  (OT * ROWQ * 16)      // 10496
#define SCX_BYTES (BT * 8)             // 4096
#define TOT_BYTES (C_BYTES + SCX_BYTES)

// ---------------- scratch (device globals; no allocation) ----------------
__device__ float4 g_cub[(size_t)IN_F * OUT_F * ROWQ];   // [i][o][41] coeffs + bw
__device__ float2 g_scx[IN_F * BATCH];                  // [i][b] (sc, silu(x)), 16B-tiles ok

// ---------------- P1: one thread per (i,o,slot); coalesced float4 stores ----------------
__global__ void prep_cub(const float* __restrict__ sw,
                         const float* __restrict__ scaler,
                         const int*   __restrict__ mask,
                         const float* __restrict__ bwp) {
    const int n  = blockIdx.x * 256 + threadIdx.x;       // = (i*OUT_F + o)*ROWQ + m
    const int io = n / ROWQ;
    const int m  = n - io * ROWQ;                        // 0..40
    const int i  = io >> 9;
    const int o  = io & (OUT_F - 1);
    const int oi = o * IN_F + i;

    float4 r;
    if (m == 40) {
        r = make_float4(bwp[oi], 0.f, 0.f, 0.f);
    } else {
        const float s  = scaler[oi];
        const bool  dm = (mask[oi] != 0);
        const float* wr = sw + (size_t)oi * NC;
        if (dm) {
            const float s6 = s * (1.f / 6.f);
            const float ys = (wr[0]  + 4.f * wr[1]  + wr[2])  * s6;
            const float ye = (wr[32] + 4.f * wr[33] + wr[34]) * s6;
            const float a  = (ye - ys) * 0.5f;           // dx = 2
            const float b0 = ys + a;                     // b = ys - a*gmin
            r = make_float4(fmaf(a, (float)(m - 20) * 0.0625f, b0),
                            a * 0.0625f, 0.f, 0.f);
        } else if (m == 0 || m == 39) {
            r = make_float4(0.f, 0.f, 0.f, 0.f);
        } else {
            const int cc = m - 4;
            const float v0 = (cc     >= 0) ? wr[cc]     * s : 0.f;
            const float v1 = (cc + 1 >= 0 && cc + 1 <= 34) ? wr[cc + 1] * s : 0.f;
            const float v2 = (cc + 2 >= 0 && cc + 2 <= 34) ? wr[cc + 2] * s : 0.f;
            const float v3 = (cc + 3 <= 34) ? wr[cc + 3] * s : 0.f;
            r.x = (v0 + 4.f * v1 + v2) * (1.f / 6.f);
            r.y = (v2 - v0) * 0.5f;
            r.z = (v0 + v2) * 0.5f - v1;
            r.w = (3.f * (v1 - v2) + (v3 - v0)) * (1.f / 6.f);
        }
    }
    g_cub[n] = r;
}

// ---------------- P2: (sc, silu) per (b,i) + zero out ----------------
__global__ void prep_bz(const float* __restrict__ x, float* __restrict__ out) {
    const int n = blockIdx.x * 256 + threadIdx.x;   // n = i*1024 + b
    const int i = n >> 10;
    const int b = n & 1023;
    const float xv = x[b * IN_F + i];
    g_scx[n] = make_float2(fmaf(xv, 16.f, 19.f), xv / (1.f + expf(-xv)));
    out[n]  = 0.f;                                  // BATCH*OUT_F == IN_F*BATCH
}

// ---------------- TMA bulk + mbarrier helpers ----------------
__device__ __forceinline__ unsigned smem_u32(const void* p) {
    return (unsigned)__cvta_generic_to_shared(p);
}
__device__ __forceinline__ void bulk_g2s(void* dst_smem, const void* src_gmem,
                                         unsigned bytes, unsigned mbar) {
    asm volatile(
        "cp.async.bulk.shared::cluster.global.mbarrier::complete_tx::bytes "
        "[%0], [%1], %2, [%3];\n"
        :: "r"(smem_u32(dst_smem)), "l"(src_gmem), "r"(bytes), "r"(mbar) : "memory");
}
#define MBAR_INIT(addr, cnt) \
    asm volatile("mbarrier.init.shared.b64 [%0], %1;" :: "r"(addr), "r"(cnt) : "memory")
#define MBAR_EXPECT_TX(addr, bytes) \
    asm volatile("mbarrier.arrive.expect_tx.shared.b64 _, [%0], %1;" \
                 :: "r"(addr), "r"(bytes) : "memory")
#define MBAR_WAIT(addr, parity) do {                                              \
    unsigned _m = (addr); unsigned _p = (parity); unsigned _done;                 \
    asm volatile("{\n\t.reg .pred p;\n\t"                                         \
        "mbarrier.try_wait.parity.acquire.cta.shared::cta.b64 p, [%1], %2;\n\t"   \
        "selp.b32 %0, 1, 0, p;\n\t}"                                              \
        : "=r"(_done) : "r"(_m), "r"(_p) : "memory");                             \
    if (!_done) {                                                                 \
        asm volatile("{\n\t.reg .pred P1;\n\t"                                    \
            "W1_%=:\n\t"                                                          \
            "mbarrier.try_wait.parity.acquire.cta.shared::cta.b64 P1, [%0], %1, 0x989680;\n\t" \
            "@P1 bra.uni W2_%=;\n\t"                                              \
            "bra.uni W1_%=;\n\t"                                                  \
            "W2_%=:\n\t}"                                                         \
            :: "r"(_m), "r"(_p) : "memory");                                      \
    }                                                                             \
} while (0)

// ---------------- main: TMA-staged, double-buffered evaluation ----------------
__global__ __launch_bounds__(512, 2) void main_k(float* __restrict__ out) {
    __shared__ __align__(16) float4 s_C[2][OT * ROWQ];   // stride-41 rows
    __shared__ __align__(16) float2 s_scx[2][BT];
    __shared__ __align__(8)  unsigned long long s_bar[2];

    const int o0   = blockIdx.x * OT;
    const int boff = blockIdx.y * BT;
    const int i0   = blockIdx.z * ICH;
    const int tid  = threadIdx.x;
    const int w    = tid >> 5;
    const int lane = tid & 31;
    const int ol   = lane & 7;
    const int bg   = lane >> 3;
    const int tb   = w * 32 + bg * 8;        // thread's first b within block tile

    const unsigned bar0 = smem_u32(&s_bar[0]);
    const unsigned bar1 = smem_u32(&s_bar[1]);

    float acc0[8], acc1[8];
    #pragma unroll
    for (int j = 0; j < 8; j++) { acc0[j] = 0.f; acc1[j] = 0.f; }

    if (tid == 0) { MBAR_INIT(bar0, 1); MBAR_INIT(bar1, 1); }
    __syncthreads();

    // producer issue (tid 0 only): stage feature i0+ii into buf
    auto issue = [&](int ii, int buf, unsigned bar) {
        const int i = i0 + ii;
        MBAR_EXPECT_TX(bar, TOT_BYTES);
        bulk_g2s(&s_C[buf][0], g_cub + ((size_t)i * OUT_F + o0) * ROWQ, C_BYTES, bar);
        bulk_g2s(&s_scx[buf][0], g_scx + i * BATCH + boff, SCX_BYTES, bar);
    };

    if (tid == 0) issue(0, 0, bar0);
    int ph0 = 0, ph1 = 0;

    for (int ii = 0; ii < ICH; ii++) {
        const int buf = ii & 1;
        // wait for this buffer's data
        if (buf == 0) { MBAR_WAIT(bar0, ph0); ph0 ^= 1; }
        else          { MBAR_WAIT(bar1, ph1); ph1 ^= 1; }

        // kick off next stage into the other buffer (safe: its last consumers
        // passed the __syncthreads at the end of iteration ii-1)
        if (tid == 0 && ii + 1 < ICH)
            issue(ii + 1, buf ^ 1, (buf == 0) ? bar1 : bar0);

        const float4* Cc = s_C[buf];
        const float bw0 = ((const float*)&Cc[ol * ROWQ + 40])[0];
        const float bw1 = ((const float*)&Cc[(ol + 8) * ROWQ + 40])[0];

        const float4* scx4 = (const float4*)&s_scx[buf][tb];
        float4 p[4];
        #pragma unroll
        for (int q = 0; q < 4; q++) p[q] = scx4[q];   // (sc,sx,sc,sx)

        #pragma unroll
        for (int j = 0; j < 8; j++) {
            const float sc = (j & 1) ? p[j >> 1].z : p[j >> 1].x;
            const float sx = (j & 1) ? p[j >> 1].w : p[j >> 1].y;
            const float sgc = fminf(fmaxf(floorf(sc), -1.f), 38.f);
            const float u  = sc - sgc;
            const int   m  = (int)sgc + 1;
            const float4 c0 = Cc[ol * ROWQ + m];
            const float4 c1 = Cc[(ol + 8) * ROWQ + m];
            acc0[j] += fmaf(bw0, sx, fmaf(fmaf(fmaf(c0.w, u, c0.z), u, c0.y), u, c0.x));
            acc1[j] += fmaf(bw1, sx, fmaf(fmaf(fmaf(c1.w, u, c1.z), u, c1.y), u, c1.x));
        }

        __syncthreads();   // all threads done reading buf -> it may be refilled
    }

    #pragma unroll
    for (int j = 0; j < 8; j++) {
        const int b = boff + tb + j;
        atomicAdd(&out[b * OUT_F + o0 + ol],     acc0[j]);
        atomicAdd(&out[b * OUT_F + o0 + ol + 8], acc1[j]);
    }
}

// ---------------- launch ----------------
extern "C" void kernel_launch(void* const* d_in, const int* in_sizes, int n_in,
                              void* d_out, int out_size) {
    const float* x      = (const float*)d_in[0];  // (1024, 512)
    const float* bw     = (const float*)d_in[1];  // (512, 512)
    const float* sw     = (const float*)d_in[2];  // (512, 512, 35)
    const float* scaler = (const float*)d_in[3];  // (512, 512)
    // d_in[4] = grid (uniform; derived analytically)
    const int*   mask   = (const int*)d_in[5];    // (512, 512)
    float* out = (float*)d_out;                   // (1024, 512)

    prep_cub<<<(IN_F * OUT_F * ROWQ) / 256, 256>>>(sw, scaler, mask, bw);
    prep_bz<<<(IN_F * BATCH) / 256, 256>>>(x, out);
    main_k<<<dim3(OUT_F / OT, BATCH / BT, NBI), 512>>>(out);
}

// round 11
// speedup vs baseline: 2.6190x; 1.0031x over previous
#include <cuda_runtime.h>
#include <cuda_bf16.h>
#include <cstdint>
#include <math.h>

#define BATCH 1024
#define IN_F  512
#define OUT_F 512
#define NC    35        // raw spline coefficients per (o,i)
#define NSEG  40        // seg 0 = below-range, 1..38 = real, 39 = above-range
#define ROWQ  41        // float4 slots per (i,o) row: 40 segments + bw in slot 40
#define OT    16        // outputs per block
#define ICH   32        // input features per block
#define NBI   (IN_F/ICH)
#define BT    512       // batches per block
#define C_BYTES  (OT * ROWQ * 16)      // 10496
#define SCX_BYTES (BT * 8)             // 4096
#define TOT_BYTES (C_BYTES + SCX_BYTES)
#define GRP   11        // 4-slot groups per row (slots 0..43, clamped at 41)

// ---------------- scratch (device globals; no allocation) ----------------
__device__ float4 g_cub[(size_t)IN_F * OUT_F * ROWQ];   // [i][o][41] coeffs + bw
__device__ float2 g_scx[IN_F * BATCH];                  // [i][b] (sc, silu(x))

// ---------------- P1: 4 slots per thread; shared taps, 64B stores ----------------
__global__ void prep_cub(const float* __restrict__ sw,
                         const float* __restrict__ scaler,
                         const int*   __restrict__ mask,
                         const float* __restrict__ bwp) {
    const int n  = blockIdx.x * 256 + threadIdx.x;   // = io*GRP + mg
    const int io = n / GRP;
    const int mg = n - io * GRP;
    const int m0 = mg * 4;                           // first slot of this group
    const int i  = io >> 9;
    const int o  = io & (OUT_F - 1);
    const int oi = o * IN_F + i;

    const float s  = scaler[oi];
    const bool  dm = (mask[oi] != 0);
    const float* wr = sw + (size_t)oi * NC;

    float4 r[4];
    if (dm) {
        const float s6 = s * (1.f / 6.f);
        const float ys = (wr[0]  + 4.f * wr[1]  + wr[2])  * s6;
        const float ye = (wr[32] + 4.f * wr[33] + wr[34]) * s6;
        const float a  = (ye - ys) * 0.5f;           // dx = 2
        const float b0 = ys + a;                     // b = ys - a*gmin
        #pragma unroll
        for (int t = 0; t < 4; t++) {
            const int m = m0 + t;
            if (m == 40) r[t] = make_float4(bwp[oi], 0.f, 0.f, 0.f);
            else         r[t] = make_float4(fmaf(a, (float)(m - 20) * 0.0625f, b0),
                                            a * 0.0625f, 0.f, 0.f);
        }
    } else {
        // taps w7[k] = s * w[m0-4+k], zeroed out-of-range; serves slots m0..m0+3
        float w7[7];
        #pragma unroll
        for (int k = 0; k < 7; k++) {
            const int c = m0 - 4 + k;
            w7[k] = (c >= 0 && c <= 34) ? wr[c] * s : 0.f;
        }
        #pragma unroll
        for (int t = 0; t < 4; t++) {
            const int m = m0 + t;
            if (m == 40) {
                r[t] = make_float4(bwp[oi], 0.f, 0.f, 0.f);
            } else if (m == 0 || m == 39) {
                r[t] = make_float4(0.f, 0.f, 0.f, 0.f);
            } else {
                const float v0 = w7[t];
                const float v1 = w7[t + 1];
                const float v2 = w7[t + 2];
                const float v3 = w7[t + 3];
                r[t].x = (v0 + 4.f * v1 + v2) * (1.f / 6.f);
                r[t].y = (v2 - v0) * 0.5f;
                r[t].z = (v0 + v2) * 0.5f - v1;
                r[t].w = (3.f * (v1 - v2) + (v3 - v0)) * (1.f / 6.f);
            }
        }
    }

    float4* dst = g_cub + (size_t)io * ROWQ + m0;
    const int nvalid = min(4, ROWQ - m0);           // mg=10 -> 1
    #pragma unroll
    for (int t = 0; t < 4; t++)
        if (t < nvalid) dst[t] = r[t];
}

// ---------------- P2: (sc, silu) per (b,i) + zero out ----------------
__global__ void prep_bz(const float* __restrict__ x, float* __restrict__ out) {
    const int n = blockIdx.x * 256 + threadIdx.x;   // n = i*1024 + b
    const int i = n >> 10;
    const int b = n & 1023;
    const float xv = x[b * IN_F + i];
    g_scx[n] = make_float2(fmaf(xv, 16.f, 19.f), xv / (1.f + expf(-xv)));
    out[n]  = 0.f;                                  // BATCH*OUT_F == IN_F*BATCH
}

// ---------------- TMA bulk + mbarrier helpers ----------------
__device__ __forceinline__ unsigned smem_u32(const void* p) {
    return (unsigned)__cvta_generic_to_shared(p);
}
__device__ __forceinline__ void bulk_g2s(void* dst_smem, const void* src_gmem,
                                         unsigned bytes, unsigned mbar) {
    asm volatile(
        "cp.async.bulk.shared::cluster.global.mbarrier::complete_tx::bytes "
        "[%0], [%1], %2, [%3];\n"
        :: "r"(smem_u32(dst_smem)), "l"(src_gmem), "r"(bytes), "r"(mbar) : "memory");
}
#define MBAR_INIT(addr, cnt) \
    asm volatile("mbarrier.init.shared.b64 [%0], %1;" :: "r"(addr), "r"(cnt) : "memory")
#define MBAR_EXPECT_TX(addr, bytes) \
    asm volatile("mbarrier.arrive.expect_tx.shared.b64 _, [%0], %1;" \
                 :: "r"(addr), "r"(bytes) : "memory")
#define MBAR_WAIT(addr, parity) do {                                              \
    unsigned _m = (addr); unsigned _p = (parity); unsigned _done;                 \
    asm volatile("{\n\t.reg .pred p;\n\t"                                         \
        "mbarrier.try_wait.parity.acquire.cta.shared::cta.b64 p, [%1], %2;\n\t"   \
        "selp.b32 %0, 1, 0, p;\n\t}"                                              \
        : "=r"(_done) : "r"(_m), "r"(_p) : "memory");                             \
    if (!_done) {                                                                 \
        asm volatile("{\n\t.reg .pred P1;\n\t"                                    \
            "W1_%=:\n\t"                                                          \
            "mbarrier.try_wait.parity.acquire.cta.shared::cta.b64 P1, [%0], %1, 0x989680;\n\t" \
            "@P1 bra.uni W2_%=;\n\t"                                              \
            "bra.uni W1_%=;\n\t"                                                  \
            "W2_%=:\n\t}"                                                         \
            :: "r"(_m), "r"(_p) : "memory");                                      \
    }                                                                             \
} while (0)

// ---------------- main: TMA-staged, double-buffered evaluation ----------------
__global__ __launch_bounds__(512, 2) void main_k(float* __restrict__ out) {
    __shared__ __align__(16) float4 s_C[2][OT * ROWQ];   // stride-41 rows
    __shared__ __align__(16) float2 s_scx[2][BT];
    __shared__ __align__(8)  unsigned long long s_bar[2];

    const int o0   = blockIdx.x * OT;
    const int boff = blockIdx.y * BT;
    const int i0   = blockIdx.z * ICH;
    const int tid  = threadIdx.x;
    const int w    = tid >> 5;
    const int lane = tid & 31;
    const int ol   = lane & 7;
    const int bg   = lane >> 3;
    const int tb   = w * 32 + bg * 8;        // thread's first b within block tile

    const unsigned bar0 = smem_u32(&s_bar[0]);
    const unsigned bar1 = smem_u32(&s_bar[1]);

    float acc0[8], acc1[8];
    #pragma unroll
    for (int j = 0; j < 8; j++) { acc0[j] = 0.f; acc1[j] = 0.f; }

    if (tid == 0) { MBAR_INIT(bar0, 1); MBAR_INIT(bar1, 1); }
    __syncthreads();

    auto issue = [&](int ii, int buf, unsigned bar) {
        const int i = i0 + ii;
        MBAR_EXPECT_TX(bar, TOT_BYTES);
        bulk_g2s(&s_C[buf][0], g_cub + ((size_t)i * OUT_F + o0) * ROWQ, C_BYTES, bar);
        bulk_g2s(&s_scx[buf][0], g_scx + i * BATCH + boff, SCX_BYTES, bar);
    };

    if (tid == 0) issue(0, 0, bar0);
    int ph0 = 0, ph1 = 0;

    for (int ii = 0; ii < ICH; ii++) {
        const int buf = ii & 1;
        if (buf == 0) { MBAR_WAIT(bar0, ph0); ph0 ^= 1; }
        else          { MBAR_WAIT(bar1, ph1); ph1 ^= 1; }

        if (tid == 0 && ii + 1 < ICH)
            issue(ii + 1, buf ^ 1, (buf == 0) ? bar1 : bar0);

        const float4* Cc = s_C[buf];
        const float bw0 = ((const float*)&Cc[ol * ROWQ + 40])[0];
        const float bw1 = ((const float*)&Cc[(ol + 8) * ROWQ + 40])[0];

        const float4* scx4 = (const float4*)&s_scx[buf][tb];
        float4 p[4];
        #pragma unroll
        for (int q = 0; q < 4; q++) p[q] = scx4[q];   // (sc,sx,sc,sx)

        #pragma unroll
        for (int j = 0; j < 8; j++) {
            const float sc = (j & 1) ? p[j >> 1].z : p[j >> 1].x;
            const float sx = (j & 1) ? p[j >> 1].w : p[j >> 1].y;
            const float sgc = fminf(fmaxf(floorf(sc), -1.f), 38.f);
            const float u  = sc - sgc;
            const int   m  = (int)sgc + 1;
            const float4 c0 = Cc[ol * ROWQ + m];
            const float4 c1 = Cc[(ol + 8) * ROWQ + m];
            acc0[j] += fmaf(bw0, sx, fmaf(fmaf(fmaf(c0.w, u, c0.z), u, c0.y), u, c0.x));
            acc1[j] += fmaf(bw1, sx, fmaf(fmaf(fmaf(c1.w, u, c1.z), u, c1.y), u, c1.x));
        }

        __syncthreads();   // all threads done reading buf -> it may be refilled
    }

    #pragma unroll
    for (int j = 0; j < 8; j++) {
        const int b = boff + tb + j;
        atomicAdd(&out[b * OUT_F + o0 + ol],     acc0[j]);
        atomicAdd(&out[b * OUT_F + o0 + ol + 8], acc1[j]);
    }
}

// ---------------- launch ----------------
extern "C" void kernel_launch(void* const* d_in, const int* in_sizes, int n_in,
                              void* d_out, int out_size) {
    const float* x      = (const float*)d_in[0];  // (1024, 512)
    const float* bw     = (const float*)d_in[1];  // (512, 512)
    const float* sw     = (const float*)d_in[2];  // (512, 512, 35)
    const float* scaler = (const float*)d_in[3];  // (512, 512)
    // d_in[4] = grid (uniform; derived analytically)
    const int*   mask   = (const int*)d_in[5];    // (512, 512)
    float* out = (float*)d_out;                   // (1024, 512)

    prep_cub<<<(IN_F * OUT_F * GRP) / 256, 256>>>(sw, scaler, mask, bw);
    prep_bz<<<(IN_F * BATCH) / 256, 256>>>(x, out);
    main_k<<<dim3(OUT_F / OT, BATCH / BT, NBI), 512>>>(out);
}

// round 12
// speedup vs baseline: 2.7872x; 1.0642x over previous
#include <cuda_runtime.h>
#include <cuda_bf16.h>
#include <cstdint>
#include <math.h>

#define BATCH 1024
#define IN_F  512
#define OUT_F 512
#define NC    35        // raw spline coefficients per (o,i)
#define NSEG  40        // seg 0 = below-range, 1..38 = real, 39 = above-range
#define ROWQ  41        // float4 slots per (i,o) row: 40 segments + bw in slot 40
#define OT    16        // outputs per block
#define ICH   32        // input features per block
#define NBI   (IN_F/ICH)
#define BT    512       // batches per block
#define C_BYTES  (OT * ROWQ * 16)      // 10496
#define SCX_BYTES (BT * 8)             // 4096
#define TOT_BYTES (C_BYTES + SCX_BYTES)
#define RB    32        // table rows (io values) per prep_cub block
#define WST   37        // smem weight row stride (floats)

// ---------------- scratch (device globals; no allocation) ----------------
__device__ float4 g_cub[(size_t)IN_F * OUT_F * ROWQ];   // [i][o][41] coeffs + bw
__device__ float2 g_scx[IN_F * BATCH];                  // [i][b] (sc, silu(x))

// ---------------- P1: smem-staged rows; coalesced reads AND writes ----------------
__global__ __launch_bounds__(256) void prep_cub(const float* __restrict__ sw,
                                                const float* __restrict__ scaler,
                                                const int*   __restrict__ mask,
                                                const float* __restrict__ bwp) {
    __shared__ float s_w[RB * WST];      // raw weights, stride-37
    __shared__ float s_scal[RB];
    __shared__ int   s_msk[RB];
    __shared__ float s_bw[RB];

    const int io0 = blockIdx.x * RB;     // first table row (io = i*OUT_F + o)
    const int tid = threadIdx.x;

    // ---- stage: coalesced within each 140B row ----
    #pragma unroll
    for (int k = 0; k < 5; k++) {
        const int idx = tid + k * 256;               // 0..1119 (RB*NC = 1120)
        if (idx < RB * NC) {
            const int r = idx / NC;
            const int c = idx - r * NC;
            const int io = io0 + r;
            const int i  = io >> 9;
            const int o  = io & (OUT_F - 1);
            s_w[r * WST + c] = sw[(size_t)(o * IN_F + i) * NC + c];
        }
    }
    if (tid < RB) {
        const int io = io0 + tid;
        const int i  = io >> 9;
        const int o  = io & (OUT_F - 1);
        const int oi = o * IN_F + i;
        s_scal[tid] = scaler[oi];
        s_msk[tid]  = mask[oi];
        s_bw[tid]   = bwp[oi];
    }
    __syncthreads();

    // ---- build + store: output-linear -> perfectly coalesced float4 ----
    #pragma unroll
    for (int k = 0; k < 6; k++) {
        const int idx = tid + k * 256;               // 0..1311 (RB*ROWQ = 1312)
        if (idx >= RB * ROWQ) break;
        const int r = idx / ROWQ;
        const int m = idx - r * ROWQ;                // 0..40
        const float s  = s_scal[r];
        const bool  dm = (s_msk[r] != 0);
        const float* wr = &s_w[r * WST];

        float4 v;
        if (m == 40) {
            v = make_float4(s_bw[r], 0.f, 0.f, 0.f);
        } else if (dm) {
            const float s6 = s * (1.f / 6.f);
            const float ys = (wr[0]  + 4.f * wr[1]  + wr[2])  * s6;
            const float ye = (wr[32] + 4.f * wr[33] + wr[34]) * s6;
            const float a  = (ye - ys) * 0.5f;       // dx = 2
            const float b0 = ys + a;                 // b = ys - a*gmin
            v = make_float4(fmaf(a, (float)(m - 20) * 0.0625f, b0),
                            a * 0.0625f, 0.f, 0.f);
        } else if (m == 0 || m == 39) {
            v = make_float4(0.f, 0.f, 0.f, 0.f);
        } else {
            const int cc = m - 4;
            const float v0 = (cc     >= 0) ? wr[cc]     * s : 0.f;
            const float v1 = (cc + 1 >= 0 && cc + 1 <= 34) ? wr[cc + 1] * s : 0.f;
            const float v2 = (cc + 2 >= 0 && cc + 2 <= 34) ? wr[cc + 2] * s : 0.f;
            const float v3 = (cc + 3 <= 34) ? wr[cc + 3] * s : 0.f;
            v.x = (v0 + 4.f * v1 + v2) * (1.f / 6.f);
            v.y = (v2 - v0) * 0.5f;
            v.z = (v0 + v2) * 0.5f - v1;
            v.w = (3.f * (v1 - v2) + (v3 - v0)) * (1.f / 6.f);
        }
        g_cub[(size_t)io0 * ROWQ + idx] = v;
    }
}

// ---------------- P2: (sc, silu) per (b,i) + zero out ----------------
__global__ void prep_bz(const float* __restrict__ x, float* __restrict__ out) {
    const int n = blockIdx.x * 256 + threadIdx.x;   // n = i*1024 + b
    const int i = n >> 10;
    const int b = n & 1023;
    const float xv = x[b * IN_F + i];
    g_scx[n] = make_float2(fmaf(xv, 16.f, 19.f), xv / (1.f + expf(-xv)));
    out[n]  = 0.f;                                  // BATCH*OUT_F == IN_F*BATCH
}

// ---------------- TMA bulk + mbarrier helpers ----------------
__device__ __forceinline__ unsigned smem_u32(const void* p) {
    return (unsigned)__cvta_generic_to_shared(p);
}
__device__ __forceinline__ void bulk_g2s(void* dst_smem, const void* src_gmem,
                                         unsigned bytes, unsigned mbar) {
    asm volatile(
        "cp.async.bulk.shared::cluster.global.mbarrier::complete_tx::bytes "
        "[%0], [%1], %2, [%3];\n"
        :: "r"(smem_u32(dst_smem)), "l"(src_gmem), "r"(bytes), "r"(mbar) : "memory");
}
#define MBAR_INIT(addr, cnt) \
    asm volatile("mbarrier.init.shared.b64 [%0], %1;" :: "r"(addr), "r"(cnt) : "memory")
#define MBAR_EXPECT_TX(addr, bytes) \
    asm volatile("mbarrier.arrive.expect_tx.shared.b64 _, [%0], %1;" \
                 :: "r"(addr), "r"(bytes) : "memory")
#define MBAR_WAIT(addr, parity) do {                                              \
    unsigned _m = (addr); unsigned _p = (parity); unsigned _done;                 \
    asm volatile("{\n\t.reg .pred p;\n\t"                                         \
        "mbarrier.try_wait.parity.acquire.cta.shared::cta.b64 p, [%1], %2;\n\t"   \
        "selp.b32 %0, 1, 0, p;\n\t}"                                              \
        : "=r"(_done) : "r"(_m), "r"(_p) : "memory");                             \
    if (!_done) {                                                                 \
        asm volatile("{\n\t.reg .pred P1;\n\t"                                    \
            "W1_%=:\n\t"                                                          \
            "mbarrier.try_wait.parity.acquire.cta.shared::cta.b64 P1, [%0], %1, 0x989680;\n\t" \
            "@P1 bra.uni W2_%=;\n\t"                                              \
            "bra.uni W1_%=;\n\t"                                                  \
            "W2_%=:\n\t}"                                                         \
            :: "r"(_m), "r"(_p) : "memory");                                      \
    }                                                                             \
} while (0)

// ---------------- main: TMA-staged, double-buffered evaluation ----------------
__global__ __launch_bounds__(512, 2) void main_k(float* __restrict__ out) {
    __shared__ __align__(16) float4 s_C[2][OT * ROWQ];   // stride-41 rows
    __shared__ __align__(16) float2 s_scx[2][BT];
    __shared__ __align__(8)  unsigned long long s_bar[2];

    const int o0   = blockIdx.x * OT;
    const int boff = blockIdx.y * BT;
    const int i0   = blockIdx.z * ICH;
    const int tid  = threadIdx.x;
    const int w    = tid >> 5;
    const int lane = tid & 31;
    const int ol   = lane & 7;
    const int bg   = lane >> 3;
    const int tb   = w * 32 + bg * 8;        // thread's first b within block tile

    const unsigned bar0 = smem_u32(&s_bar[0]);
    const unsigned bar1 = smem_u32(&s_bar[1]);

    float acc0[8], acc1[8];
    #pragma unroll
    for (int j = 0; j < 8; j++) { acc0[j] = 0.f; acc1[j] = 0.f; }

    if (tid == 0) { MBAR_INIT(bar0, 1); MBAR_INIT(bar1, 1); }
    __syncthreads();

    auto issue = [&](int ii, int buf, unsigned bar) {
        const int i = i0 + ii;
        MBAR_EXPECT_TX(bar, TOT_BYTES);
        bulk_g2s(&s_C[buf][0], g_cub + ((size_t)i * OUT_F + o0) * ROWQ, C_BYTES, bar);
        bulk_g2s(&s_scx[buf][0], g_scx + i * BATCH + boff, SCX_BYTES, bar);
    };

    if (tid == 0) issue(0, 0, bar0);
    int ph0 = 0, ph1 = 0;

    for (int ii = 0; ii < ICH; ii++) {
        const int buf = ii & 1;
        if (buf == 0) { MBAR_WAIT(bar0, ph0); ph0 ^= 1; }
        else          { MBAR_WAIT(bar1, ph1); ph1 ^= 1; }

        if (tid == 0 && ii + 1 < ICH)
            issue(ii + 1, buf ^ 1, (buf == 0) ? bar1 : bar0);

        const float4* Cc = s_C[buf];
        const float bw0 = ((const float*)&Cc[ol * ROWQ + 40])[0];
        const float bw1 = ((const float*)&Cc[(ol + 8) * ROWQ + 40])[0];

        const float4* scx4 = (const float4*)&s_scx[buf][tb];
        float4 p[4];
        #pragma unroll
        for (int q = 0; q < 4; q++) p[q] = scx4[q];   // (sc,sx,sc,sx)

        #pragma unroll
        for (int j = 0; j < 8; j++) {
            const float sc = (j & 1) ? p[j >> 1].z : p[j >> 1].x;
            const float sx = (j & 1) ? p[j >> 1].w : p[j >> 1].y;
            const float sgc = fminf(fmaxf(floorf(sc), -1.f), 38.f);
            const float u  = sc - sgc;
            const int   m  = (int)sgc + 1;
            const float4 c0 = Cc[ol * ROWQ + m];
            const float4 c1 = Cc[(ol + 8) * ROWQ + m];
            acc0[j] += fmaf(bw0, sx, fmaf(fmaf(fmaf(c0.w, u, c0.z), u, c0.y), u, c0.x));
            acc1[j] += fmaf(bw1, sx, fmaf(fmaf(fmaf(c1.w, u, c1.z), u, c1.y), u, c1.x));
        }

        __syncthreads();   // all threads done reading buf -> it may be refilled
    }

    #pragma unroll
    for (int j = 0; j < 8; j++) {
        const int b = boff + tb + j;
        atomicAdd(&out[b * OUT_F + o0 + ol],     acc0[j]);
        atomicAdd(&out[b * OUT_F + o0 + ol + 8], acc1[j]);
    }
}

// ---------------- launch ----------------
extern "C" void kernel_launch(void* const* d_in, const int* in_sizes, int n_in,
                              void* d_out, int out_size) {
    const float* x      = (const float*)d_in[0];  // (1024, 512)
    const float* bw     = (const float*)d_in[1];  // (512, 512)
    const float* sw     = (const float*)d_in[2];  // (512, 512, 35)
    const float* scaler = (const float*)d_in[3];  // (512, 512)
    // d_in[4] = grid (uniform; derived analytically)
    const int*   mask   = (const int*)d_in[5];    // (512, 512)
    float* out = (float*)d_out;                   // (1024, 512)

    prep_cub<<<(IN_F * OUT_F) / RB, 256>>>(sw, scaler, mask, bw);
    prep_bz<<<(IN_F * BATCH) / 256, 256>>>(x, out);
    main_k<<<dim3(OUT_F / OT, BATCH / BT, NBI), 512>>>(out);
}